// round 3
// baseline (speedup 1.0000x reference)
#include <cuda_runtime.h>

#define Bdim 4
#define Nseq 2048
#define Dmod 512
#define Hn   8
#define En   64
#define Mtot (Bdim*Nseq)                 // 8192
#define BHNE ((size_t)Bdim*Hn*Nseq*En)   // 4194304

// ---------------- scratch (device globals; no allocations) ----------------
__device__ float g_xn [(size_t)Mtot*Dmod];
__device__ float g_q  [BHNE];
__device__ float g_k  [BHNE];
__device__ float g_v  [BHNE];
__device__ float g_g  [BHNE];
__device__ float g_att[(size_t)Mtot*Dmod];
__device__ float g_tmp[(size_t)Mtot*Dmod];

// ---------------- LayerNorm: one block per row (D=512), 128 thr ----------------
__global__ void ln_kernel(const float* __restrict__ in,
                          const float* __restrict__ gamma,
                          const float* __restrict__ beta,
                          float* __restrict__ out)
{
    int row = blockIdx.x;
    int tid = threadIdx.x;                 // 128 threads, 4 floats each
    const float4 v = ((const float4*)(in + (size_t)row * Dmod))[tid];
    __shared__ float red[4];

    float s = v.x + v.y + v.z + v.w;
    #pragma unroll
    for (int off = 16; off; off >>= 1) s += __shfl_xor_sync(0xffffffffu, s, off);
    if ((tid & 31) == 0) red[tid >> 5] = s;
    __syncthreads();
    float mean = (red[0] + red[1] + red[2] + red[3]) * (1.f / 512.f);

    float dx0 = v.x - mean, dx1 = v.y - mean, dx2 = v.z - mean, dx3 = v.w - mean;
    float ss = dx0*dx0 + dx1*dx1 + dx2*dx2 + dx3*dx3;
    __syncthreads();
    #pragma unroll
    for (int off = 16; off; off >>= 1) ss += __shfl_xor_sync(0xffffffffu, ss, off);
    if ((tid & 31) == 0) red[tid >> 5] = ss;
    __syncthreads();
    float var = (red[0] + red[1] + red[2] + red[3]) * (1.f / 512.f);
    float rstd = rsqrtf(var + 1e-6f);

    const float4 gm = ((const float4*)gamma)[tid];
    const float4 bt = ((const float4*)beta)[tid];
    float4 r;
    r.x = gm.x * dx0 * rstd + bt.x;
    r.y = gm.y * dx1 * rstd + bt.y;
    r.z = gm.z * dx2 * rstd + bt.z;
    r.w = gm.w * dx3 * rstd + bt.w;
    ((float4*)(out + (size_t)row * Dmod))[tid] = r;
}

// ---------------- Projection GEMM: [8192,512] x W[h,512,64] -> [B,H,N,E] ------
// 64x64 tile, K-chunk 32, 256 threads, 4x4 per thread.
// mode: 0 = plain (Q,K,V)  [reference RoPE rotates q,k identically per head ->
//                           exactly cancels in q.k; omitted on purpose]
// mode: 2 = sigmoid (gate)
__global__ __launch_bounds__(256) void proj_gemm(
    const float* __restrict__ A, const float* __restrict__ W,
    float* __restrict__ out, int mode)
{
    __shared__ float As[64][33];
    __shared__ float Bs[32][68];
    int tid  = threadIdx.x;
    int m0   = blockIdx.x * 64;
    int head = blockIdx.y;                  // n-tile == one head (64 cols)
    int tm = (tid >> 4) << 2;
    int tn = (tid & 15) << 2;
    float c[4][4] = {};

    for (int k0 = 0; k0 < Dmod; k0 += 32) {
        __syncthreads();
        #pragma unroll
        for (int l = 0; l < 8; l++) {
            int idx = l * 256 + tid;
            As[idx >> 5][idx & 31] =
                A[(size_t)(m0 + (idx >> 5)) * Dmod + k0 + (idx & 31)];
            Bs[idx >> 6][idx & 63] =
                W[(size_t)head * Dmod * En + (size_t)(k0 + (idx >> 6)) * En + (idx & 63)];
        }
        __syncthreads();
        #pragma unroll
        for (int kk = 0; kk < 32; kk++) {
            float a0 = As[tm][kk], a1 = As[tm+1][kk], a2 = As[tm+2][kk], a3 = As[tm+3][kk];
            float4 b = *(const float4*)&Bs[kk][tn];
            c[0][0] += a0*b.x; c[0][1] += a0*b.y; c[0][2] += a0*b.z; c[0][3] += a0*b.w;
            c[1][0] += a1*b.x; c[1][1] += a1*b.y; c[1][2] += a1*b.z; c[1][3] += a1*b.w;
            c[2][0] += a2*b.x; c[2][1] += a2*b.y; c[2][2] += a2*b.z; c[2][3] += a2*b.w;
            c[3][0] += a3*b.x; c[3][1] += a3*b.y; c[3][2] += a3*b.z; c[3][3] += a3*b.w;
        }
    }

    #pragma unroll
    for (int i = 0; i < 4; i++) {
        int r  = m0 + tm + i;
        int n  = r & (Nseq - 1);
        int bb = r >> 11;
        float v0 = c[i][0], v1 = c[i][1], v2 = c[i][2], v3 = c[i][3];
        if (mode == 2) {
            v0 = 1.f / (1.f + __expf(-v0));
            v1 = 1.f / (1.f + __expf(-v1));
            v2 = 1.f / (1.f + __expf(-v2));
            v3 = 1.f / (1.f + __expf(-v3));
        }
        float* op = out + (((size_t)(bb * Hn + head) * Nseq + n) * En + tn);
        op[0] = v0; op[1] = v1; op[2] = v2; op[3] = v3;
    }
}

// ---------------- Output GEMM: att[8192,512] x out_w[512,512] + bias + resid --
__global__ __launch_bounds__(256) void out_gemm(
    const float* __restrict__ A, const float* __restrict__ W,
    const float* __restrict__ bias, const float* __restrict__ resid,
    float* __restrict__ out)
{
    __shared__ float As[64][33];
    __shared__ float Bs[32][68];
    int tid = threadIdx.x;
    int m0  = blockIdx.x * 64;
    int n0  = blockIdx.y * 64;
    int tm = (tid >> 4) << 2;
    int tn = (tid & 15) << 2;
    float c[4][4] = {};

    for (int k0 = 0; k0 < Dmod; k0 += 32) {
        __syncthreads();
        #pragma unroll
        for (int l = 0; l < 8; l++) {
            int idx = l * 256 + tid;
            As[idx >> 5][idx & 31] =
                A[(size_t)(m0 + (idx >> 5)) * Dmod + k0 + (idx & 31)];
            Bs[idx >> 6][idx & 63] =
                W[(size_t)(k0 + (idx >> 6)) * Dmod + n0 + (idx & 63)];
        }
        __syncthreads();
        #pragma unroll
        for (int kk = 0; kk < 32; kk++) {
            float a0 = As[tm][kk], a1 = As[tm+1][kk], a2 = As[tm+2][kk], a3 = As[tm+3][kk];
            float4 b = *(const float4*)&Bs[kk][tn];
            c[0][0] += a0*b.x; c[0][1] += a0*b.y; c[0][2] += a0*b.z; c[0][3] += a0*b.w;
            c[1][0] += a1*b.x; c[1][1] += a1*b.y; c[1][2] += a1*b.z; c[1][3] += a1*b.w;
            c[2][0] += a2*b.x; c[2][1] += a2*b.y; c[2][2] += a2*b.z; c[2][3] += a2*b.w;
            c[3][0] += a3*b.x; c[3][1] += a3*b.y; c[3][2] += a3*b.z; c[3][3] += a3*b.w;
        }
    }

    #pragma unroll
    for (int i = 0; i < 4; i++) {
        int r = m0 + tm + i;
        #pragma unroll
        for (int j = 0; j < 4; j++) {
            int col = n0 + tn + j;
            out[(size_t)r * Dmod + col] = c[i][j] + bias[col] + resid[(size_t)r * Dmod + col];
        }
    }
}

// ---------------- Flash attention (fp32, online softmax) ----------------------
// grid (N/128, B*H), 256 threads: 2 threads per query row, each owns 32 e-cols.
__global__ __launch_bounds__(256, 1) void attn_kernel(
    const float* __restrict__ Q, const float* __restrict__ K,
    const float* __restrict__ V, const float* __restrict__ G,
    const float* __restrict__ mask, float* __restrict__ out)
{
    __shared__ float Ks[32 * 64];
    __shared__ float Vs[32 * 64];
    __shared__ float mk[32];

    int tid  = threadIdx.x;
    int bh   = blockIdx.y;
    int bb   = bh >> 3;
    int row  = (blockIdx.x << 7) + (tid >> 1);
    int half = tid & 1;

    const float* Qb = Q + (size_t)bh * Nseq * En;
    const float* Kb = K + (size_t)bh * Nseq * En;
    const float* Vb = V + (size_t)bh * Nseq * En;

    float4 q[8];
    {
        const float4* qp = (const float4*)(Qb + (size_t)row * En + half * 32);
        #pragma unroll
        for (int i = 0; i < 8; i++) q[i] = qp[i];
    }
    float4 o[8];
    #pragma unroll
    for (int i = 0; i < 8; i++) o[i] = make_float4(0.f, 0.f, 0.f, 0.f);

    float m = -1e30f, l = 0.f;
    const float scale = 0.125f;   // 1/sqrt(64)

    for (int kt = 0; kt < Nseq / 32; kt++) {
        __syncthreads();
        {
            const float4* ksrc = (const float4*)(Kb + (size_t)kt * 32 * En);
            const float4* vsrc = (const float4*)(Vb + (size_t)kt * 32 * En);
            float4* kd = (float4*)Ks; float4* vd = (float4*)Vs;
            kd[tid] = ksrc[tid]; kd[tid + 256] = ksrc[tid + 256];
            vd[tid] = vsrc[tid]; vd[tid + 256] = vsrc[tid + 256];
            if (tid < 32) mk[tid] = (mask[bb * Nseq + kt * 32 + tid] > 0.f) ? 1.f : 0.f;
        }
        __syncthreads();

        float s[32];
        #pragma unroll
        for (int j = 0; j < 32; j++) {
            const float4* kr = (const float4*)(Ks + j * 64 + half * 32);
            float acc = 0.f;
            #pragma unroll
            for (int i = 0; i < 8; i++) {
                float4 kv = kr[i];
                acc += q[i].x * kv.x + q[i].y * kv.y + q[i].z * kv.z + q[i].w * kv.w;
            }
            s[j] = acc;
        }
        #pragma unroll
        for (int j = 0; j < 32; j++) s[j] += __shfl_xor_sync(0xffffffffu, s[j], 1);

        float mt = m;
        #pragma unroll
        for (int j = 0; j < 32; j++) {
            s[j] = s[j] * scale + (1.f - mk[j]) * (-1e9f);
            mt = fmaxf(mt, s[j]);
        }
        float corr = __expf(m - mt);
        m = mt;
        l *= corr;
        #pragma unroll
        for (int i = 0; i < 8; i++) {
            o[i].x *= corr; o[i].y *= corr; o[i].z *= corr; o[i].w *= corr;
        }
        #pragma unroll
        for (int j = 0; j < 32; j++) {
            float p = __expf(s[j] - m);
            l += p;
            const float4* vr = (const float4*)(Vs + j * 64 + half * 32);
            #pragma unroll
            for (int i = 0; i < 8; i++) {
                float4 vv = vr[i];
                o[i].x += p * vv.x; o[i].y += p * vv.y; o[i].z += p * vv.z; o[i].w += p * vv.w;
            }
        }
    }

    float qm  = (mask[bb * Nseq + row] > 0.f) ? 1.f : 0.f;
    float rcp = (l > 0.f) ? (qm / l) : 0.f;

    const float4* gp = (const float4*)(G + ((size_t)bh * Nseq + row) * En + half * 32);
    float4* op = (float4*)(out + ((size_t)(bb * Nseq + row)) * Dmod + (bh & 7) * En + half * 32);
    #pragma unroll
    for (int i = 0; i < 8; i++) {
        float4 gg = gp[i];
        float4 r;
        r.x = o[i].x * rcp * gg.x;
        r.y = o[i].y * rcp * gg.y;
        r.z = o[i].z * rcp * gg.z;
        r.w = o[i].w * rcp * gg.w;
        op[i] = r;
    }
}

// ---------------- launch --------------------------------------------------
extern "C" void kernel_launch(void* const* d_in, const int* in_sizes, int n_in,
                              void* d_out, int out_size)
{
    const float* x         = (const float*)d_in[0];
    const float* mask      = (const float*)d_in[1];
    const float* q_proj    = (const float*)d_in[2];
    const float* k_proj    = (const float*)d_in[3];
    const float* v_proj    = (const float*)d_in[4];
    const float* g_w       = (const float*)d_in[5];
    const float* gamma_in  = (const float*)d_in[6];
    const float* beta_in   = (const float*)d_in[7];
    const float* gamma_out = (const float*)d_in[8];
    const float* beta_out  = (const float*)d_in[9];
    const float* out_w     = (const float*)d_in[10];
    const float* out_b     = (const float*)d_in[11];

    float *xn, *qb, *kb, *vb, *gb, *ab, *tb;
    cudaGetSymbolAddress((void**)&xn, g_xn);
    cudaGetSymbolAddress((void**)&qb, g_q);
    cudaGetSymbolAddress((void**)&kb, g_k);
    cudaGetSymbolAddress((void**)&vb, g_v);
    cudaGetSymbolAddress((void**)&gb, g_g);
    cudaGetSymbolAddress((void**)&ab, g_att);
    cudaGetSymbolAddress((void**)&tb, g_tmp);

    // 1) input LayerNorm
    ln_kernel<<<Mtot, 128>>>(x, gamma_in, beta_in, xn);

    // 2) Q/K/V/G projections. NOTE: reference RoPE rotates q and k by a
    //    head-indexed angle (seq = x.shape[1] = H), identical for q and k of
    //    the same head -> orthogonal rotation cancels exactly in q.k^T, so it
    //    is mathematically a no-op and intentionally omitted.
    dim3 ggrid(Mtot / 64, Hn);
    proj_gemm<<<ggrid, 256>>>(xn, q_proj, qb, 0);
    proj_gemm<<<ggrid, 256>>>(xn, k_proj, kb, 0);
    proj_gemm<<<ggrid, 256>>>(xn, v_proj, vb, 0);
    proj_gemm<<<ggrid, 256>>>(xn, g_w,    gb, 2);

    // 3) masked flash attention + gate, writes [B,N,H*E]
    attn_kernel<<<dim3(Nseq / 128, Bdim * Hn), 256>>>(qb, kb, vb, gb, mask, ab);

    // 4) output projection + bias + residual
    out_gemm<<<dim3(Mtot / 64, Dmod / 64), 256>>>(ab, out_w, out_b, x, tb);

    // 5) output LayerNorm
    ln_kernel<<<Mtot, 128>>>(tb, gamma_out, beta_out, (float*)d_out);
}

// round 5
// speedup vs baseline: 2.4684x; 2.4684x over previous
#include <cuda_runtime.h>
#include <cuda_bf16.h>
#include <cstdint>

#define Bdim 4
#define Nseq 2048
#define Dmod 512
#define Hn   8
#define En   64
#define Mtot (Bdim*Nseq)
#define BHNE ((size_t)Bdim*Hn*Nseq*En)

__device__ float g_xn [(size_t)Mtot*Dmod];
__device__ float g_q  [BHNE];
__device__ float g_k  [BHNE];
__device__ float g_v  [BHNE];
__device__ float g_g  [BHNE];
__device__ float g_att[(size_t)Mtot*Dmod];
__device__ float g_tmp[(size_t)Mtot*Dmod];

// =============== helpers ===============
__device__ __forceinline__ void mma_bf16(float* c, const uint32_t* a, const uint32_t* b) {
    asm volatile("mma.sync.aligned.m16n8k16.row.col.f32.bf16.bf16.f32 "
        "{%0,%1,%2,%3}, {%4,%5,%6,%7}, {%8,%9}, {%0,%1,%2,%3};"
        : "+f"(c[0]), "+f"(c[1]), "+f"(c[2]), "+f"(c[3])
        : "r"(a[0]), "r"(a[1]), "r"(a[2]), "r"(a[3]), "r"(b[0]), "r"(b[1]));
}
__device__ __forceinline__ uint32_t packbf(__nv_bfloat16 lo, __nv_bfloat16 hi) {
    return ((uint32_t)__bfloat16_as_ushort(hi) << 16) | __bfloat16_as_ushort(lo);
}

#define ATT_T 4608   // 64 rows * 72 bf16 per staged tile
#define ATT_SMEM (6*ATT_T*2 + 256)

// ---------- warp-MMA flash attention: grid(32, B*H), 128 thr ----------
// CTA: 64 q-rows of one (b,h). 4 warps x 16 rows. K-tiles of 64 keys.
// S = Q K^T and O += P V via mma.sync bf16 with split hi/lo (3-term) fp32-grade precision.
__global__ __launch_bounds__(128) void attn_mma(
    const float* __restrict__ Q, const float* __restrict__ K,
    const float* __restrict__ V, const float* __restrict__ G,
    const float* __restrict__ mask, float* __restrict__ out)
{
    extern __shared__ __nv_bfloat16 smb[];
    __nv_bfloat16 *Qh = smb,           *Ql = smb + ATT_T,
                  *Kh = smb + 2*ATT_T, *Kl = smb + 3*ATT_T,
                  *Vh = smb + 4*ATT_T, *Vl = smb + 5*ATT_T;   // Vh/Vl are TRANSPOSED: [e][key]
    float* bias = (float*)(smb + 6*ATT_T);

    const int tid = threadIdx.x, wid = tid >> 5, lid = tid & 31;
    const int g = lid >> 2, qp = (lid & 3) * 2;
    const int qt = blockIdx.x, bh = blockIdx.y, bb = bh >> 3, hh = bh & 7;

    const float* Qg = Q + ((size_t)bh * Nseq + (size_t)qt * 64) * 64;
    const float* Kg = K + (size_t)bh * Nseq * 64;
    const float* Vg = V + (size_t)bh * Nseq * 64;

    // ---- stage Q tile (hi/lo), stride 72 ----
    for (int idx = tid; idx < 64 * 32; idx += 128) {
        int r = idx >> 5, cp = (idx & 31) * 2;
        float2 f = *(const float2*)(Qg + (size_t)r * 64 + cp);
        __nv_bfloat16 h0 = __float2bfloat16_rn(f.x), h1 = __float2bfloat16_rn(f.y);
        __nv_bfloat16 e0 = __float2bfloat16_rn(f.x - __bfloat162float(h0));
        __nv_bfloat16 e1 = __float2bfloat16_rn(f.y - __bfloat162float(h1));
        *(uint32_t*)(Qh + r * 72 + cp) = packbf(h0, h1);
        *(uint32_t*)(Ql + r * 72 + cp) = packbf(e0, e1);
    }
    __syncthreads();

    // ---- preload Q A-fragments (reused for all K tiles) ----
    uint32_t qfh[4][4], qfl[4][4];
    {
        int ar = wid * 16 + g;
        #pragma unroll
        for (int kk = 0; kk < 4; kk++) {
            int c0 = kk * 16 + qp;
            qfh[kk][0] = *(const uint32_t*)(Qh + ar * 72 + c0);
            qfh[kk][1] = *(const uint32_t*)(Qh + (ar + 8) * 72 + c0);
            qfh[kk][2] = *(const uint32_t*)(Qh + ar * 72 + c0 + 8);
            qfh[kk][3] = *(const uint32_t*)(Qh + (ar + 8) * 72 + c0 + 8);
            qfl[kk][0] = *(const uint32_t*)(Ql + ar * 72 + c0);
            qfl[kk][1] = *(const uint32_t*)(Ql + (ar + 8) * 72 + c0);
            qfl[kk][2] = *(const uint32_t*)(Ql + ar * 72 + c0 + 8);
            qfl[kk][3] = *(const uint32_t*)(Ql + (ar + 8) * 72 + c0 + 8);
        }
    }

    float O[8][4];
    #pragma unroll
    for (int i = 0; i < 8; i++) { O[i][0]=0.f; O[i][1]=0.f; O[i][2]=0.f; O[i][3]=0.f; }
    float ps0 = 0.f, ps1 = 0.f;

    for (int t = 0; t < 32; t++) {
        __syncthreads();
        // ---- stage K (row-major) and V (transposed) hi/lo ----
        const float* Ks = Kg + (size_t)t * 64 * 64;
        const float* Vs = Vg + (size_t)t * 64 * 64;
        for (int idx = tid; idx < 64 * 32; idx += 128) {
            int r = idx >> 5, cp = (idx & 31) * 2;
            float2 f = *(const float2*)(Ks + (size_t)r * 64 + cp);
            __nv_bfloat16 h0 = __float2bfloat16_rn(f.x), h1 = __float2bfloat16_rn(f.y);
            __nv_bfloat16 e0 = __float2bfloat16_rn(f.x - __bfloat162float(h0));
            __nv_bfloat16 e1 = __float2bfloat16_rn(f.y - __bfloat162float(h1));
            *(uint32_t*)(Kh + r * 72 + cp) = packbf(h0, h1);
            *(uint32_t*)(Kl + r * 72 + cp) = packbf(e0, e1);
            float2 v = *(const float2*)(Vs + (size_t)r * 64 + cp);
            __nv_bfloat16 vh0 = __float2bfloat16_rn(v.x), vh1 = __float2bfloat16_rn(v.y);
            __nv_bfloat16 ve0 = __float2bfloat16_rn(v.x - __bfloat162float(vh0));
            __nv_bfloat16 ve1 = __float2bfloat16_rn(v.y - __bfloat162float(vh1));
            Vh[cp * 72 + r] = vh0; Vh[(cp + 1) * 72 + r] = vh1;
            Vl[cp * 72 + r] = ve0; Vl[(cp + 1) * 72 + r] = ve1;
        }
        if (tid < 64)
            bias[tid] = (mask[bb * Nseq + t * 64 + tid] > 0.f) ? 0.f : -1e9f;
        __syncthreads();

        // ---- S = Q K^T (3-term split) ----
        float cS[8][4];
        #pragma unroll
        for (int i = 0; i < 8; i++) { cS[i][0]=0.f; cS[i][1]=0.f; cS[i][2]=0.f; cS[i][3]=0.f; }
        #pragma unroll
        for (int nt = 0; nt < 8; nt++) {
            int kb = (nt * 8 + g) * 72 + qp;
            #pragma unroll
            for (int kk = 0; kk < 4; kk++) {
                uint32_t b2h[2], b2l[2];
                const __nv_bfloat16* kp = Kh + kb + kk * 16;
                b2h[0] = *(const uint32_t*)kp; b2h[1] = *(const uint32_t*)(kp + 8);
                kp = Kl + kb + kk * 16;
                b2l[0] = *(const uint32_t*)kp; b2l[1] = *(const uint32_t*)(kp + 8);
                mma_bf16(cS[nt], qfh[kk], b2h);
                mma_bf16(cS[nt], qfh[kk], b2l);
                mma_bf16(cS[nt], qfl[kk], b2h);
            }
        }

        // ---- softmax (no max-sub; masked -> exact 0) + pack P into A-frags ----
        uint32_t ahi[4][4], alo[4][4];
        #pragma unroll
        for (int nt = 0; nt < 8; nt++) {
            float b0 = bias[nt * 8 + qp], b1 = bias[nt * 8 + qp + 1];
            float p0 = __expf(fmaf(cS[nt][0], 0.125f, b0));
            float p1 = __expf(fmaf(cS[nt][1], 0.125f, b1));
            float p2 = __expf(fmaf(cS[nt][2], 0.125f, b0));
            float p3 = __expf(fmaf(cS[nt][3], 0.125f, b1));
            ps0 += p0 + p1; ps1 += p2 + p3;
            __nv_bfloat16 h0 = __float2bfloat16_rn(p0), h1 = __float2bfloat16_rn(p1);
            __nv_bfloat16 h2 = __float2bfloat16_rn(p2), h3 = __float2bfloat16_rn(p3);
            __nv_bfloat16 l0 = __float2bfloat16_rn(p0 - __bfloat162float(h0));
            __nv_bfloat16 l1 = __float2bfloat16_rn(p1 - __bfloat162float(h1));
            __nv_bfloat16 l2 = __float2bfloat16_rn(p2 - __bfloat162float(h2));
            __nv_bfloat16 l3 = __float2bfloat16_rn(p3 - __bfloat162float(h3));
            int kk = nt >> 1, o = (nt & 1) * 2;
            ahi[kk][o]     = packbf(h0, h1);   // row g,   k-low
            ahi[kk][o + 1] = packbf(h2, h3);   // row g+8, k-low
            alo[kk][o]     = packbf(l0, l1);
            alo[kk][o + 1] = packbf(l2, l3);
        }

        // ---- O += P V (3-term split), V transposed in smem ----
        #pragma unroll
        for (int nt = 0; nt < 8; nt++) {
            int vb = (nt * 8 + g) * 72 + qp;
            #pragma unroll
            for (int kk = 0; kk < 4; kk++) {
                uint32_t b2h[2], b2l[2];
                const __nv_bfloat16* vp = Vh + vb + kk * 16;
                b2h[0] = *(const uint32_t*)vp; b2h[1] = *(const uint32_t*)(vp + 8);
                vp = Vl + vb + kk * 16;
                b2l[0] = *(const uint32_t*)vp; b2l[1] = *(const uint32_t*)(vp + 8);
                mma_bf16(O[nt], ahi[kk], b2h);
                mma_bf16(O[nt], ahi[kk], b2l);
                mma_bf16(O[nt], alo[kk], b2h);
            }
        }
    }

    // ---- epilogue: row sums, gate, qmask ----
    ps0 += __shfl_xor_sync(0xffffffffu, ps0, 1);
    ps0 += __shfl_xor_sync(0xffffffffu, ps0, 2);
    ps1 += __shfl_xor_sync(0xffffffffu, ps1, 1);
    ps1 += __shfl_xor_sync(0xffffffffu, ps1, 2);

    int n0 = qt * 64 + wid * 16 + g, n1 = n0 + 8;
    float qm0 = (mask[bb * Nseq + n0] > 0.f) ? 1.f : 0.f;
    float qm1 = (mask[bb * Nseq + n1] > 0.f) ? 1.f : 0.f;
    float rc0 = (ps0 > 0.f) ? qm0 / ps0 : 0.f;
    float rc1 = (ps1 > 0.f) ? qm1 / ps1 : 0.f;

    const float* G0 = G + ((size_t)bh * Nseq + n0) * 64;
    const float* G1 = G + ((size_t)bh * Nseq + n1) * 64;
    float* O0 = out + ((size_t)bb * Nseq + n0) * Dmod + hh * 64;
    float* O1 = out + ((size_t)bb * Nseq + n1) * Dmod + hh * 64;
    #pragma unroll
    for (int nt = 0; nt < 8; nt++) {
        int col = nt * 8 + qp;
        float2 g0 = *(const float2*)(G0 + col);
        float2 g1 = *(const float2*)(G1 + col);
        float2 w0, w1;
        w0.x = O[nt][0] * rc0 * g0.x; w0.y = O[nt][1] * rc0 * g0.y;
        w1.x = O[nt][2] * rc1 * g1.x; w1.y = O[nt][3] * rc1 * g1.y;
        *(float2*)(O0 + col) = w0;
        *(float2*)(O1 + col) = w1;
    }
}

// ---------------- LayerNorm ----------------
__global__ void ln_kernel(const float* __restrict__ in,
                          const float* __restrict__ gamma,
                          const float* __restrict__ beta,
                          float* __restrict__ out)
{
    int row = blockIdx.x;
    int tid = threadIdx.x;
    const float4 v = ((const float4*)(in + (size_t)row * Dmod))[tid];
    __shared__ float red[4];

    float s = v.x + v.y + v.z + v.w;
    #pragma unroll
    for (int off = 16; off; off >>= 1) s += __shfl_xor_sync(0xffffffffu, s, off);
    if ((tid & 31) == 0) red[tid >> 5] = s;
    __syncthreads();
    float mean = (red[0] + red[1] + red[2] + red[3]) * (1.f / 512.f);

    float dx0 = v.x - mean, dx1 = v.y - mean, dx2 = v.z - mean, dx3 = v.w - mean;
    float ss = dx0*dx0 + dx1*dx1 + dx2*dx2 + dx3*dx3;
    __syncthreads();
    #pragma unroll
    for (int off = 16; off; off >>= 1) ss += __shfl_xor_sync(0xffffffffu, ss, off);
    if ((tid & 31) == 0) red[tid >> 5] = ss;
    __syncthreads();
    float var = (red[0] + red[1] + red[2] + red[3]) * (1.f / 512.f);
    float rstd = rsqrtf(var + 1e-6f);

    const float4 gm = ((const float4*)gamma)[tid];
    const float4 bt = ((const float4*)beta)[tid];
    float4 r;
    r.x = gm.x * dx0 * rstd + bt.x;
    r.y = gm.y * dx1 * rstd + bt.y;
    r.z = gm.z * dx2 * rstd + bt.z;
    r.w = gm.w * dx3 * rstd + bt.w;
    ((float4*)(out + (size_t)row * Dmod))[tid] = r;
}

// ---------------- Projection GEMM (unchanged) ----------------
__global__ __launch_bounds__(256) void proj_gemm(
    const float* __restrict__ A, const float* __restrict__ W,
    float* __restrict__ out, int mode)
{
    __shared__ float As[64][33];
    __shared__ float Bs[32][68];
    int tid  = threadIdx.x;
    int m0   = blockIdx.x * 64;
    int head = blockIdx.y;
    int tm = (tid >> 4) << 2;
    int tn = (tid & 15) << 2;
    float c[4][4] = {};

    for (int k0 = 0; k0 < Dmod; k0 += 32) {
        __syncthreads();
        #pragma unroll
        for (int l = 0; l < 8; l++) {
            int idx = l * 256 + tid;
            As[idx >> 5][idx & 31] = A[(size_t)(m0 + (idx >> 5)) * Dmod + k0 + (idx & 31)];
            Bs[idx >> 6][idx & 63] = W[(size_t)head * Dmod * En + (size_t)(k0 + (idx >> 6)) * En + (idx & 63)];
        }
        __syncthreads();
        #pragma unroll
        for (int kk = 0; kk < 32; kk++) {
            float a0 = As[tm][kk], a1 = As[tm+1][kk], a2 = As[tm+2][kk], a3 = As[tm+3][kk];
            float4 b = *(const float4*)&Bs[kk][tn];
            c[0][0] += a0*b.x; c[0][1] += a0*b.y; c[0][2] += a0*b.z; c[0][3] += a0*b.w;
            c[1][0] += a1*b.x; c[1][1] += a1*b.y; c[1][2] += a1*b.z; c[1][3] += a1*b.w;
            c[2][0] += a2*b.x; c[2][1] += a2*b.y; c[2][2] += a2*b.z; c[2][3] += a2*b.w;
            c[3][0] += a3*b.x; c[3][1] += a3*b.y; c[3][2] += a3*b.z; c[3][3] += a3*b.w;
        }
    }

    #pragma unroll
    for (int i = 0; i < 4; i++) {
        int r  = m0 + tm + i;
        int n  = r & (Nseq - 1);
        int bb = r >> 11;
        float v0 = c[i][0], v1 = c[i][1], v2 = c[i][2], v3 = c[i][3];
        if (mode == 2) {
            v0 = 1.f / (1.f + __expf(-v0));
            v1 = 1.f / (1.f + __expf(-v1));
            v2 = 1.f / (1.f + __expf(-v2));
            v3 = 1.f / (1.f + __expf(-v3));
        }
        float* op = out + (((size_t)(bb * Hn + head) * Nseq + n) * En + tn);
        op[0] = v0; op[1] = v1; op[2] = v2; op[3] = v3;
    }
}

// ---------------- Output GEMM (unchanged) ----------------
__global__ __launch_bounds__(256) void out_gemm(
    const float* __restrict__ A, const float* __restrict__ W,
    const float* __restrict__ bias, const float* __restrict__ resid,
    float* __restrict__ out)
{
    __shared__ float As[64][33];
    __shared__ float Bs[32][68];
    int tid = threadIdx.x;
    int m0  = blockIdx.x * 64;
    int n0  = blockIdx.y * 64;
    int tm = (tid >> 4) << 2;
    int tn = (tid & 15) << 2;
    float c[4][4] = {};

    for (int k0 = 0; k0 < Dmod; k0 += 32) {
        __syncthreads();
        #pragma unroll
        for (int l = 0; l < 8; l++) {
            int idx = l * 256 + tid;
            As[idx >> 5][idx & 31] = A[(size_t)(m0 + (idx >> 5)) * Dmod + k0 + (idx & 31)];
            Bs[idx >> 6][idx & 63] = W[(size_t)(k0 + (idx >> 6)) * Dmod + n0 + (idx & 63)];
        }
        __syncthreads();
        #pragma unroll
        for (int kk = 0; kk < 32; kk++) {
            float a0 = As[tm][kk], a1 = As[tm+1][kk], a2 = As[tm+2][kk], a3 = As[tm+3][kk];
            float4 b = *(const float4*)&Bs[kk][tn];
            c[0][0] += a0*b.x; c[0][1] += a0*b.y; c[0][2] += a0*b.z; c[0][3] += a0*b.w;
            c[1][0] += a1*b.x; c[1][1] += a1*b.y; c[1][2] += a1*b.z; c[1][3] += a1*b.w;
            c[2][0] += a2*b.x; c[2][1] += a2*b.y; c[2][2] += a2*b.z; c[2][3] += a2*b.w;
            c[3][0] += a3*b.x; c[3][1] += a3*b.y; c[3][2] += a3*b.z; c[3][3] += a3*b.w;
        }
    }

    #pragma unroll
    for (int i = 0; i < 4; i++) {
        int r = m0 + tm + i;
        #pragma unroll
        for (int j = 0; j < 4; j++) {
            int col = n0 + tn + j;
            out[(size_t)r * Dmod + col] = c[i][j] + bias[col] + resid[(size_t)r * Dmod + col];
        }
    }
}

// ---------------- launch ----------------
extern "C" void kernel_launch(void* const* d_in, const int* in_sizes, int n_in,
                              void* d_out, int out_size)
{
    const float* x         = (const float*)d_in[0];
    const float* mask      = (const float*)d_in[1];
    const float* q_proj    = (const float*)d_in[2];
    const float* k_proj    = (const float*)d_in[3];
    const float* v_proj    = (const float*)d_in[4];
    const float* g_w       = (const float*)d_in[5];
    const float* gamma_in  = (const float*)d_in[6];
    const float* beta_in   = (const float*)d_in[7];
    const float* gamma_out = (const float*)d_in[8];
    const float* beta_out  = (const float*)d_in[9];
    const float* out_w     = (const float*)d_in[10];
    const float* out_b     = (const float*)d_in[11];

    float *xn, *qb, *kb, *vb, *gb, *ab, *tb;
    cudaGetSymbolAddress((void**)&xn, g_xn);
    cudaGetSymbolAddress((void**)&qb, g_q);
    cudaGetSymbolAddress((void**)&kb, g_k);
    cudaGetSymbolAddress((void**)&vb, g_v);
    cudaGetSymbolAddress((void**)&gb, g_g);
    cudaGetSymbolAddress((void**)&ab, g_att);
    cudaGetSymbolAddress((void**)&tb, g_tmp);

    ln_kernel<<<Mtot, 128>>>(x, gamma_in, beta_in, xn);

    // Reference RoPE rotates q,k identically per head (seq==H bug) -> cancels in q.k^T.
    dim3 ggrid(Mtot / 64, Hn);
    proj_gemm<<<ggrid, 256>>>(xn, q_proj, qb, 0);
    proj_gemm<<<ggrid, 256>>>(xn, k_proj, kb, 0);
    proj_gemm<<<ggrid, 256>>>(xn, v_proj, vb, 0);
    proj_gemm<<<ggrid, 256>>>(xn, g_w,    gb, 2);

    cudaFuncSetAttribute(attn_mma, cudaFuncAttributeMaxDynamicSharedMemorySize, ATT_SMEM);
    attn_mma<<<dim3(Nseq / 64, Bdim * Hn), 128, ATT_SMEM>>>(qb, kb, vb, gb, mask, ab);

    out_gemm<<<dim3(Mtot / 64, Dmod / 64), 256>>>(ab, out_w, out_b, x, tb);
    ln_kernel<<<Mtot, 128>>>(tb, gamma_out, beta_out, (float*)d_out);
}